// round 7
// baseline (speedup 1.0000x reference)
#include <cuda_runtime.h>

#define E_DIM 8
#define F_DIM 32
#define TPT 2          // tokens per thread
#define THREADS 256

using u64 = unsigned long long;

__device__ __forceinline__ u64 pack2(float lo, float hi) {
    u64 r;
    asm("mov.b64 %0, {%1, %2};" : "=l"(r) : "f"(lo), "f"(hi));
    return r;
}
__device__ __forceinline__ void unpack2(u64 v, float& lo, float& hi) {
    asm("mov.b64 {%0, %1}, %2;" : "=f"(lo), "=f"(hi) : "l"(v));
}
// Packed dual fp32 FMA (Blackwell f32x2 pipe).
__device__ __forceinline__ u64 fma2(u64 a, u64 b, u64 c) {
    u64 d;
    asm("fma.rn.f32x2 %0, %1, %2, %3;" : "=l"(d) : "l"(a), "l"(b), "l"(c));
    return d;
}
// relu on a packed pair, in place (2 FMNMX, no packing movs needed).
__device__ __forceinline__ u64 relu2(u64 v) {
    float lo, hi;
    unpack2(v, lo, hi);
    lo = fmaxf(lo, 0.0f);
    hi = fmaxf(hi, 0.0f);
    return pack2(lo, hi);
}
// horizontal sum of a packed pair.
__device__ __forceinline__ float hsum2(u64 v) {
    float lo, hi;
    unpack2(v, lo, hi);
    return lo + hi;
}

__global__ void __launch_bounds__(THREADS, 3)
ffq_kernel(const float* __restrict__ x,
           const float* __restrict__ theta,
           const float* __restrict__ w1,    // [E][F] row-major
           const float* __restrict__ b1,    // [F]
           const float* __restrict__ w2,    // [F][E] row-major
           const float* __restrict__ b2,    // [E]
           float* __restrict__ out,
           long long n_tokens)
{
    // All weights in smem; every in-loop read is a warp-uniform broadcast
    // (conflict-free, LDS structural floor only). No constant port, no
    // memcpy graph nodes.
    __shared__ __align__(16) u64 sw1t[16 * 8];  // [f2][i]: (w1[i][2f2], w1[i][2f2+1])
    __shared__ __align__(16) u64 sw2i[16 * 8];  // [f2][e]: (w2[2f2][e], w2[2f2+1][e])
    __shared__ __align__(16) u64 sb1[16];       // b1 pairs
    __shared__ __align__(16) u64 sb2p[8];       // (b2[e], 0)
    __shared__ float sth[E_DIM];

    const int t = threadIdx.x;
    if (t < 128) {
        // w1 transpose into f2-major pair layout (u64 copy keeps the pair).
        const int f2 = t >> 3, i = t & 7;
        sw1t[t] = ((const u64*)w1)[i * 16 + f2];
    } else {
        // w2 interleave: pair over adjacent F rows for fixed e.
        const int idx = t - 128, f2 = idx >> 3, e = idx & 7;
        sw2i[idx] = pack2(w2[(2 * f2) * E_DIM + e], w2[(2 * f2 + 1) * E_DIM + e]);
    }
    if (t < 16)       sb1[t]     = ((const u64*)b1)[t];
    else if (t < 24)  sb2p[t-16] = pack2(b2[t - 16], 0.0f);
    else if (t < 32)  sth[t-24]  = theta[t - 24];
    __syncthreads();

    const long long token0 = ((long long)blockIdx.x * THREADS + t) * TPT;
    if (token0 + 1 >= n_tokens) return;   // exact grid in practice

    // ---- load x for 2 tokens: 64 contiguous bytes ----
    const float4* xp = (const float4*)(x + token0 * E_DIM);
    float4 a0 = xp[0], a1 = xp[1], a2 = xp[2], a3 = xp[3];

    // ---- quantum layer: q = cos(x + theta), packed (q,q) broadcast ----
    u64 q0[E_DIM], q1[E_DIM];
    {
        float c;
        c = __cosf(a0.x + sth[0]); q0[0] = pack2(c, c);
        c = __cosf(a0.y + sth[1]); q0[1] = pack2(c, c);
        c = __cosf(a0.z + sth[2]); q0[2] = pack2(c, c);
        c = __cosf(a0.w + sth[3]); q0[3] = pack2(c, c);
        c = __cosf(a1.x + sth[4]); q0[4] = pack2(c, c);
        c = __cosf(a1.y + sth[5]); q0[5] = pack2(c, c);
        c = __cosf(a1.z + sth[6]); q0[6] = pack2(c, c);
        c = __cosf(a1.w + sth[7]); q0[7] = pack2(c, c);
        c = __cosf(a2.x + sth[0]); q1[0] = pack2(c, c);
        c = __cosf(a2.y + sth[1]); q1[1] = pack2(c, c);
        c = __cosf(a2.z + sth[2]); q1[2] = pack2(c, c);
        c = __cosf(a2.w + sth[3]); q1[3] = pack2(c, c);
        c = __cosf(a3.x + sth[4]); q1[4] = pack2(c, c);
        c = __cosf(a3.y + sth[5]); q1[5] = pack2(c, c);
        c = __cosf(a3.z + sth[6]); q1[6] = pack2(c, c);
        c = __cosf(a3.w + sth[7]); q1[7] = pack2(c, c);
    }

    // ---- outputs: 8 accumulators per token, packed over F pairs.
    // init (b2[e], 0): final hsum folds in the bias for free. ----
    u64 o0[E_DIM], o1[E_DIM];
#pragma unroll
    for (int e = 0; e < E_DIM; e++) { o0[e] = sb2p[e]; o1[e] = o0[e]; }

    // ---- fused MLP: one (f, f+1) column pair per iteration ----
#pragma unroll
    for (int f2 = 0; f2 < F_DIM / 2; f2++) {
        // layer 1: h pair = b1 pair + sum_i q_i * w1[i][pair]
        u64 h0 = sb1[f2], h1 = h0;
        {
            ulonglong2 wA = *(const ulonglong2*)&sw1t[f2 * 8 + 0];  // i=0,1
            ulonglong2 wB = *(const ulonglong2*)&sw1t[f2 * 8 + 2];  // i=2,3
            h0 = fma2(q0[0], wA.x, h0);  h1 = fma2(q1[0], wA.x, h1);
            h0 = fma2(q0[1], wA.y, h0);  h1 = fma2(q1[1], wA.y, h1);
            h0 = fma2(q0[2], wB.x, h0);  h1 = fma2(q1[2], wB.x, h1);
            h0 = fma2(q0[3], wB.y, h0);  h1 = fma2(q1[3], wB.y, h1);
        }
        {
            ulonglong2 wC = *(const ulonglong2*)&sw1t[f2 * 8 + 4];  // i=4,5
            ulonglong2 wD = *(const ulonglong2*)&sw1t[f2 * 8 + 6];  // i=6,7
            h0 = fma2(q0[4], wC.x, h0);  h1 = fma2(q1[4], wC.x, h1);
            h0 = fma2(q0[5], wC.y, h0);  h1 = fma2(q1[5], wC.y, h1);
            h0 = fma2(q0[6], wD.x, h0);  h1 = fma2(q1[6], wD.x, h1);
            h0 = fma2(q0[7], wD.y, h0);  h1 = fma2(q1[7], wD.y, h1);
        }

        // relu (packed in place) — h stays a (f, f+1) pair
        h0 = relu2(h0);
        h1 = relu2(h1);

        // layer 2: o[e] += h_pair * (w2[f][e], w2[f+1][e])
        {
            ulonglong2 vA = *(const ulonglong2*)&sw2i[f2 * 8 + 0];  // e=0,1
            ulonglong2 vB = *(const ulonglong2*)&sw2i[f2 * 8 + 2];  // e=2,3
            o0[0] = fma2(h0, vA.x, o0[0]);  o1[0] = fma2(h1, vA.x, o1[0]);
            o0[1] = fma2(h0, vA.y, o0[1]);  o1[1] = fma2(h1, vA.y, o1[1]);
            o0[2] = fma2(h0, vB.x, o0[2]);  o1[2] = fma2(h1, vB.x, o1[2]);
            o0[3] = fma2(h0, vB.y, o0[3]);  o1[3] = fma2(h1, vB.y, o1[3]);
        }
        {
            ulonglong2 vC = *(const ulonglong2*)&sw2i[f2 * 8 + 4];  // e=4,5
            ulonglong2 vD = *(const ulonglong2*)&sw2i[f2 * 8 + 6];  // e=6,7
            o0[4] = fma2(h0, vC.x, o0[4]);  o1[4] = fma2(h1, vC.x, o1[4]);
            o0[5] = fma2(h0, vC.y, o0[5]);  o1[5] = fma2(h1, vC.y, o1[5]);
            o0[6] = fma2(h0, vD.x, o0[6]);  o1[6] = fma2(h1, vD.x, o1[6]);
            o0[7] = fma2(h0, vD.y, o0[7]);  o1[7] = fma2(h1, vD.y, o1[7]);
        }
    }

    // ---- epilogue: horizontal sums (bias already inside), store 64 B ----
    float4 r0, r1, r2, r3;
    r0.x = hsum2(o0[0]); r0.y = hsum2(o0[1]); r0.z = hsum2(o0[2]); r0.w = hsum2(o0[3]);
    r1.x = hsum2(o0[4]); r1.y = hsum2(o0[5]); r1.z = hsum2(o0[6]); r1.w = hsum2(o0[7]);
    r2.x = hsum2(o1[0]); r2.y = hsum2(o1[1]); r2.z = hsum2(o1[2]); r2.w = hsum2(o1[3]);
    r3.x = hsum2(o1[4]); r3.y = hsum2(o1[5]); r3.z = hsum2(o1[6]); r3.w = hsum2(o1[7]);
    float4* op = (float4*)(out + token0 * E_DIM);
    op[0] = r0; op[1] = r1; op[2] = r2; op[3] = r3;
}

extern "C" void kernel_launch(void* const* d_in, const int* in_sizes, int n_in,
                              void* d_out, int out_size) {
    const float* x     = (const float*)d_in[0];
    const float* theta = (const float*)d_in[1];
    const float* w1    = (const float*)d_in[2];
    const float* b1    = (const float*)d_in[3];
    const float* w2    = (const float*)d_in[4];
    const float* b2    = (const float*)d_in[5];
    float* out         = (float*)d_out;

    const long long n_tokens = (long long)in_sizes[0] / E_DIM;  // B*S
    const long long pairs    = n_tokens / TPT;
    const int blocks         = (int)((pairs + THREADS - 1) / THREADS);

    // Single graph node — no weight staging.
    ffq_kernel<<<blocks, THREADS>>>(x, theta, w1, b1, w2, b2, out, n_tokens);
}

// round 9
// speedup vs baseline: 1.1162x; 1.1162x over previous
#include <cuda_runtime.h>

#define E_DIM 8
#define F_DIM 32
#define TPT 2          // tokens per thread
#define THREADS 256

using u64 = unsigned long long;

// Single packed parameter blob: gathered gmem->gmem by a prep kernel, then one
// D2D memcpy into the constant bank. All in-loop weight reads are LDC.128 on
// the dedicated constant port (2 cyc/SM each vs 4 for broadcast LDS.128).
struct __align__(16) CBlob {
    float w1[E_DIM * F_DIM];   // [E][F] row-major
    float w2[F_DIM * E_DIM];   // [F][E] row-major
    float b1[F_DIM];
    float b2[E_DIM];
    float th[E_DIM];
    float pad[4];
};

__device__   CBlob g_blob;     // gmem staging (written by prep kernel)
__constant__ CBlob c_blob;     // read by main kernel

__global__ void prep_kernel(const float* __restrict__ theta,
                            const float* __restrict__ w1,
                            const float* __restrict__ b1,
                            const float* __restrict__ w2,
                            const float* __restrict__ b2)
{
    const int t = threadIdx.x;                      // 256 threads
    g_blob.w1[t] = w1[t];                           // 256 elements
    g_blob.w2[t] = w2[t];                           // 256 elements
    if (t < F_DIM)                    g_blob.b1[t] = b1[t];
    else if (t < F_DIM + E_DIM)       g_blob.b2[t - F_DIM] = b2[t - F_DIM];
    else if (t < F_DIM + 2 * E_DIM)   g_blob.th[t - F_DIM - E_DIM] =
                                          theta[t - F_DIM - E_DIM];
}

__device__ __forceinline__ u64 pack2(float lo, float hi) {
    u64 r;
    asm("mov.b64 %0, {%1, %2};" : "=l"(r) : "f"(lo), "f"(hi));
    return r;
}
__device__ __forceinline__ void unpack2(u64 v, float& lo, float& hi) {
    asm("mov.b64 {%0, %1}, %2;" : "=f"(lo), "=f"(hi) : "l"(v));
}
// Packed dual fp32 FMA (Blackwell f32x2 pipe).
__device__ __forceinline__ u64 fma2(u64 a, u64 b, u64 c) {
    u64 d;
    asm("fma.rn.f32x2 %0, %1, %2, %3;" : "=l"(d) : "l"(a), "l"(b), "l"(c));
    return d;
}

__global__ void __launch_bounds__(THREADS, 5)
ffq_kernel(const float* __restrict__ x,
           float* __restrict__ out,
           long long n_tokens)
{
    const long long token0 =
        ((long long)blockIdx.x * THREADS + threadIdx.x) * TPT;
    if (token0 + 1 >= n_tokens) return;   // exact grid in practice

    // ---- load x for 2 tokens: 64 contiguous bytes ----
    const float4* xp = (const float4*)(x + token0 * E_DIM);
    float4 a0 = xp[0], a1 = xp[1], a2 = xp[2], a3 = xp[3];

    // ---- quantum layer: q = cos(x + theta), pre-packed (q,q) ----
    u64 q0[E_DIM], q1[E_DIM];
    {
        float c;
        c = __cosf(a0.x + c_blob.th[0]); q0[0] = pack2(c, c);
        c = __cosf(a0.y + c_blob.th[1]); q0[1] = pack2(c, c);
        c = __cosf(a0.z + c_blob.th[2]); q0[2] = pack2(c, c);
        c = __cosf(a0.w + c_blob.th[3]); q0[3] = pack2(c, c);
        c = __cosf(a1.x + c_blob.th[4]); q0[4] = pack2(c, c);
        c = __cosf(a1.y + c_blob.th[5]); q0[5] = pack2(c, c);
        c = __cosf(a1.z + c_blob.th[6]); q0[6] = pack2(c, c);
        c = __cosf(a1.w + c_blob.th[7]); q0[7] = pack2(c, c);
        c = __cosf(a2.x + c_blob.th[0]); q1[0] = pack2(c, c);
        c = __cosf(a2.y + c_blob.th[1]); q1[1] = pack2(c, c);
        c = __cosf(a2.z + c_blob.th[2]); q1[2] = pack2(c, c);
        c = __cosf(a2.w + c_blob.th[3]); q1[3] = pack2(c, c);
        c = __cosf(a3.x + c_blob.th[4]); q1[4] = pack2(c, c);
        c = __cosf(a3.y + c_blob.th[5]); q1[5] = pack2(c, c);
        c = __cosf(a3.z + c_blob.th[6]); q1[6] = pack2(c, c);
        c = __cosf(a3.w + c_blob.th[7]); q1[7] = pack2(c, c);
    }

    // ---- output accumulators: packed E pairs, init with b2 ----
    u64 o0[E_DIM / 2], o1[E_DIM / 2];
    {
        float4 ba = *(const float4*)&c_blob.b2[0];
        float4 bb = *(const float4*)&c_blob.b2[4];
        o0[0] = pack2(ba.x, ba.y); o0[1] = pack2(ba.z, ba.w);
        o0[2] = pack2(bb.x, bb.y); o0[3] = pack2(bb.z, bb.w);
        o1[0] = o0[0]; o1[1] = o0[1]; o1[2] = o0[2]; o1[3] = o0[3];
    }

    // ---- fused layer1+layer2, 4 F-columns per iteration ----
#pragma unroll
    for (int f4 = 0; f4 < F_DIM / 4; f4++) {
        // layer 1: h for 4 f-values (two packed pairs) per token
        float4 bb = *(const float4*)&c_blob.b1[f4 * 4];          // LDC.128
        u64 hA0 = pack2(bb.x, bb.y), hB0 = pack2(bb.z, bb.w);
        u64 hA1 = hA0, hB1 = hB0;
#pragma unroll
        for (int i = 0; i < E_DIM; i++) {
            float4 w = *(const float4*)&c_blob.w1[i * F_DIM + f4 * 4];  // LDC.128
            u64 wA = pack2(w.x, w.y), wB = pack2(w.z, w.w);
            hA0 = fma2(q0[i], wA, hA0);
            hB0 = fma2(q0[i], wB, hB0);
            hA1 = fma2(q1[i], wA, hA1);
            hB1 = fma2(q1[i], wB, hB1);
        }

        // relu + layer 2 for these 4 f-values
        float h0[4], h1[4];
        unpack2(hA0, h0[0], h0[1]); unpack2(hB0, h0[2], h0[3]);
        unpack2(hA1, h1[0], h1[1]); unpack2(hB1, h1[2], h1[3]);
#pragma unroll
        for (int j = 0; j < 4; j++) {
            const int f = f4 * 4 + j;
            float d0 = fmaxf(h0[j], 0.0f);
            float d1 = fmaxf(h1[j], 0.0f);
            u64 p0 = pack2(d0, d0), p1 = pack2(d1, d1);
            float4 wa = *(const float4*)&c_blob.w2[f * E_DIM];       // LDC.128
            float4 wb = *(const float4*)&c_blob.w2[f * E_DIM + 4];   // LDC.128
            u64 w01 = pack2(wa.x, wa.y), w23 = pack2(wa.z, wa.w);
            u64 w45 = pack2(wb.x, wb.y), w67 = pack2(wb.z, wb.w);
            o0[0] = fma2(p0, w01, o0[0]);
            o0[1] = fma2(p0, w23, o0[1]);
            o0[2] = fma2(p0, w45, o0[2]);
            o0[3] = fma2(p0, w67, o0[3]);
            o1[0] = fma2(p1, w01, o1[0]);
            o1[1] = fma2(p1, w23, o1[1]);
            o1[2] = fma2(p1, w45, o1[2]);
            o1[3] = fma2(p1, w67, o1[3]);
        }
    }

    // ---- store 2 tokens: 64 contiguous bytes ----
    float4 r0, r1, r2, r3;
    unpack2(o0[0], r0.x, r0.y); unpack2(o0[1], r0.z, r0.w);
    unpack2(o0[2], r1.x, r1.y); unpack2(o0[3], r1.z, r1.w);
    unpack2(o1[0], r2.x, r2.y); unpack2(o1[1], r2.z, r2.w);
    unpack2(o1[2], r3.x, r3.y); unpack2(o1[3], r3.z, r3.w);
    float4* op = (float4*)(out + token0 * E_DIM);
    op[0] = r0; op[1] = r1; op[2] = r2; op[3] = r3;
}

extern "C" void kernel_launch(void* const* d_in, const int* in_sizes, int n_in,
                              void* d_out, int out_size) {
    const float* x     = (const float*)d_in[0];
    const float* theta = (const float*)d_in[1];
    const float* w1    = (const float*)d_in[2];
    const float* b1    = (const float*)d_in[3];
    const float* w2    = (const float*)d_in[4];
    const float* b2    = (const float*)d_in[5];
    float* out         = (float*)d_out;

    // Node 1: gather the five small inputs into one contiguous gmem blob.
    prep_kernel<<<1, THREADS>>>(theta, w1, b1, w2, b2);

    // Node 2: single D2D copy blob -> constant bank.
    void* src = nullptr;
    void* dst = nullptr;
    (void)cudaGetSymbolAddress(&src, g_blob);
    (void)cudaGetSymbolAddress(&dst, c_blob);
    cudaMemcpyAsync(dst, src, sizeof(CBlob), cudaMemcpyDeviceToDevice, 0);

    // Node 3: main kernel.
    const long long n_tokens = (long long)in_sizes[0] / E_DIM;  // B*S
    const long long pairs    = n_tokens / TPT;
    const int blocks         = (int)((pairs + THREADS - 1) / THREADS);
    ffq_kernel<<<blocks, THREADS>>>(x, out, n_tokens);
}

// round 10
// speedup vs baseline: 1.2949x; 1.1602x over previous
#include <cuda_runtime.h>

#define E_DIM 8
#define F_DIM 32
#define TPT 2          // tokens per thread
#define THREADS 256

using u64 = unsigned long long;

// Parameter blob in the constant bank. The prep kernel writes the blob's
// BACKING memory directly (constant symbols are ordinary global memory behind
// the dedicated constant cache; that cache is invalidated at launch
// boundaries, which is the same coherence contract the memcpyToSymbol DMA
// path depends on). This removes the copy-engine memcpy node from the graph.
struct __align__(16) CBlob {
    float w1[E_DIM * F_DIM];   // [E][F] row-major
    float w2[F_DIM * E_DIM];   // [F][E] row-major
    float b1[F_DIM];
    float b2[E_DIM];
    float th[E_DIM];
    float pad[4];
};

__constant__ CBlob c_blob;

__global__ void prep_kernel(float* __restrict__ dst_blob,   // = &c_blob backing
                            const float* __restrict__ theta,
                            const float* __restrict__ w1,
                            const float* __restrict__ b1,
                            const float* __restrict__ w2,
                            const float* __restrict__ b2)
{
    CBlob* b = (CBlob*)dst_blob;
    const int t = threadIdx.x;                      // 256 threads
    b->w1[t] = w1[t];                               // 256 elements
    b->w2[t] = w2[t];                               // 256 elements
    if (t < F_DIM)                    b->b1[t] = b1[t];
    else if (t < F_DIM + E_DIM)       b->b2[t - F_DIM] = b2[t - F_DIM];
    else if (t < F_DIM + 2 * E_DIM)   b->th[t - F_DIM - E_DIM] =
                                          theta[t - F_DIM - E_DIM];
}

__device__ __forceinline__ u64 pack2(float lo, float hi) {
    u64 r;
    asm("mov.b64 %0, {%1, %2};" : "=l"(r) : "f"(lo), "f"(hi));
    return r;
}
__device__ __forceinline__ void unpack2(u64 v, float& lo, float& hi) {
    asm("mov.b64 {%0, %1}, %2;" : "=f"(lo), "=f"(hi) : "l"(v));
}
// Packed dual fp32 FMA (Blackwell f32x2 pipe).
__device__ __forceinline__ u64 fma2(u64 a, u64 b, u64 c) {
    u64 d;
    asm("fma.rn.f32x2 %0, %1, %2, %3;" : "=l"(d) : "l"(a), "l"(b), "l"(c));
    return d;
}

__global__ void __launch_bounds__(THREADS, 5)
ffq_kernel(const float* __restrict__ x,
           float* __restrict__ out,
           long long n_tokens)
{
    const long long token0 =
        ((long long)blockIdx.x * THREADS + threadIdx.x) * TPT;
    if (token0 + 1 >= n_tokens) return;   // exact grid in practice

    // ---- load x for 2 tokens: 64 contiguous bytes ----
    const float4* xp = (const float4*)(x + token0 * E_DIM);
    float4 a0 = xp[0], a1 = xp[1], a2 = xp[2], a3 = xp[3];

    // ---- quantum layer: q = cos(x + theta), pre-packed (q,q) ----
    u64 q0[E_DIM], q1[E_DIM];
    {
        float c;
        c = __cosf(a0.x + c_blob.th[0]); q0[0] = pack2(c, c);
        c = __cosf(a0.y + c_blob.th[1]); q0[1] = pack2(c, c);
        c = __cosf(a0.z + c_blob.th[2]); q0[2] = pack2(c, c);
        c = __cosf(a0.w + c_blob.th[3]); q0[3] = pack2(c, c);
        c = __cosf(a1.x + c_blob.th[4]); q0[4] = pack2(c, c);
        c = __cosf(a1.y + c_blob.th[5]); q0[5] = pack2(c, c);
        c = __cosf(a1.z + c_blob.th[6]); q0[6] = pack2(c, c);
        c = __cosf(a1.w + c_blob.th[7]); q0[7] = pack2(c, c);
        c = __cosf(a2.x + c_blob.th[0]); q1[0] = pack2(c, c);
        c = __cosf(a2.y + c_blob.th[1]); q1[1] = pack2(c, c);
        c = __cosf(a2.z + c_blob.th[2]); q1[2] = pack2(c, c);
        c = __cosf(a2.w + c_blob.th[3]); q1[3] = pack2(c, c);
        c = __cosf(a3.x + c_blob.th[4]); q1[4] = pack2(c, c);
        c = __cosf(a3.y + c_blob.th[5]); q1[5] = pack2(c, c);
        c = __cosf(a3.z + c_blob.th[6]); q1[6] = pack2(c, c);
        c = __cosf(a3.w + c_blob.th[7]); q1[7] = pack2(c, c);
    }

    // ---- output accumulators: packed E pairs, init with b2 ----
    u64 o0[E_DIM / 2], o1[E_DIM / 2];
    {
        float4 ba = *(const float4*)&c_blob.b2[0];
        float4 bb = *(const float4*)&c_blob.b2[4];
        o0[0] = pack2(ba.x, ba.y); o0[1] = pack2(ba.z, ba.w);
        o0[2] = pack2(bb.x, bb.y); o0[3] = pack2(bb.z, bb.w);
        o1[0] = o0[0]; o1[1] = o0[1]; o1[2] = o0[2]; o1[3] = o0[3];
    }

    // ---- fused layer1+layer2, 4 F-columns per iteration ----
#pragma unroll
    for (int f4 = 0; f4 < F_DIM / 4; f4++) {
        // layer 1: h for 4 f-values (two packed pairs) per token
        float4 bb = *(const float4*)&c_blob.b1[f4 * 4];          // LDC.128
        u64 hA0 = pack2(bb.x, bb.y), hB0 = pack2(bb.z, bb.w);
        u64 hA1 = hA0, hB1 = hB0;
#pragma unroll
        for (int i = 0; i < E_DIM; i++) {
            float4 w = *(const float4*)&c_blob.w1[i * F_DIM + f4 * 4];  // LDC.128
            u64 wA = pack2(w.x, w.y), wB = pack2(w.z, w.w);
            hA0 = fma2(q0[i], wA, hA0);
            hB0 = fma2(q0[i], wB, hB0);
            hA1 = fma2(q1[i], wA, hA1);
            hB1 = fma2(q1[i], wB, hB1);
        }

        // relu + layer 2 for these 4 f-values
        float h0[4], h1[4];
        unpack2(hA0, h0[0], h0[1]); unpack2(hB0, h0[2], h0[3]);
        unpack2(hA1, h1[0], h1[1]); unpack2(hB1, h1[2], h1[3]);
#pragma unroll
        for (int j = 0; j < 4; j++) {
            const int f = f4 * 4 + j;
            float d0 = fmaxf(h0[j], 0.0f);
            float d1 = fmaxf(h1[j], 0.0f);
            u64 p0 = pack2(d0, d0), p1 = pack2(d1, d1);
            float4 wa = *(const float4*)&c_blob.w2[f * E_DIM];       // LDC.128
            float4 wb = *(const float4*)&c_blob.w2[f * E_DIM + 4];   // LDC.128
            u64 w01 = pack2(wa.x, wa.y), w23 = pack2(wa.z, wa.w);
            u64 w45 = pack2(wb.x, wb.y), w67 = pack2(wb.z, wb.w);
            o0[0] = fma2(p0, w01, o0[0]);
            o0[1] = fma2(p0, w23, o0[1]);
            o0[2] = fma2(p0, w45, o0[2]);
            o0[3] = fma2(p0, w67, o0[3]);
            o1[0] = fma2(p1, w01, o1[0]);
            o1[1] = fma2(p1, w23, o1[1]);
            o1[2] = fma2(p1, w45, o1[2]);
            o1[3] = fma2(p1, w67, o1[3]);
        }
    }

    // ---- store 2 tokens: 64 contiguous bytes ----
    float4 r0, r1, r2, r3;
    unpack2(o0[0], r0.x, r0.y); unpack2(o0[1], r0.z, r0.w);
    unpack2(o0[2], r1.x, r1.y); unpack2(o0[3], r1.z, r1.w);
    unpack2(o1[0], r2.x, r2.y); unpack2(o1[1], r2.z, r2.w);
    unpack2(o1[2], r3.x, r3.y); unpack2(o1[3], r3.z, r3.w);
    float4* op = (float4*)(out + token0 * E_DIM);
    op[0] = r0; op[1] = r1; op[2] = r2; op[3] = r3;
}

extern "C" void kernel_launch(void* const* d_in, const int* in_sizes, int n_in,
                              void* d_out, int out_size) {
    const float* x     = (const float*)d_in[0];
    const float* theta = (const float*)d_in[1];
    const float* w1    = (const float*)d_in[2];
    const float* b1    = (const float*)d_in[3];
    const float* w2    = (const float*)d_in[4];
    const float* b2    = (const float*)d_in[5];
    float* out         = (float*)d_out;

    // Resolve the constant symbol's backing address (host API, not stream
    // work — legal during capture).
    void* blob_dev = nullptr;
    (void)cudaGetSymbolAddress(&blob_dev, c_blob);

    // Node 1: gather inputs straight into the constant bank's backing store.
    prep_kernel<<<1, THREADS>>>((float*)blob_dev, theta, w1, b1, w2, b2);

    // Node 2: main kernel (constant cache refetches after launch boundary).
    const long long n_tokens = (long long)in_sizes[0] / E_DIM;  // B*S
    const long long pairs    = n_tokens / TPT;
    const int blocks         = (int)((pairs + THREADS - 1) / THREADS);
    ffq_kernel<<<blocks, THREADS>>>(x, out, n_tokens);
}